// round 4
// baseline (speedup 1.0000x reference)
#include <cuda_runtime.h>
#include <math.h>

// Problem constants
#define BB   256
#define NN   2048
#define RR   64
#define DD   64
#define TT   8
#define KD   128
#define HH   128
#define LMAX 64
#define TM   64
#define XP   68   // transposed smem pitch (floats): 68*4=272B, 16B-aligned rows

typedef unsigned long long ull;

// ---------------- device scratch ----------------
__device__ int           g_cnt[LMAX * TT];
__device__ int           g_start[LMAX * TT + 1];
__device__ int           g_cursor[LMAX * TT];
__device__ unsigned char g_lvl[BB * NN];
__device__ unsigned int  g_list[BB * (NN - RR)];
__device__ int           g_maxlvl;
__device__ int           g_bar_count;
__device__ volatile int  g_bar_gen;

// ---------------- f32x2 helpers ----------------
__device__ __forceinline__ ull pack2(float a, float b) {
    ull r; asm("mov.b64 %0, {%1, %2};" : "=l"(r) : "f"(a), "f"(b)); return r;
}
__device__ __forceinline__ ull bcast2(float a) { return pack2(a, a); }
__device__ __forceinline__ void unpack2(ull v, float& a, float& b) {
    asm("mov.b64 {%0, %1}, %2;" : "=f"(a), "=f"(b) : "l"(v));
}
__device__ __forceinline__ ull fma2(ull a, ull b, ull c) {
    ull d; asm("fma.rn.f32x2 %0, %1, %2, %3;" : "=l"(d) : "l"(a), "l"(b), "l"(c));
    return d;
}
__device__ __forceinline__ float gelu_exact(float v) {
    return 0.5f * v * (1.0f + erff(v * 0.70710678118654752f));
}

// ---------------- K0: zero counters ----------------
__global__ void k_zero() {
    g_cnt[threadIdx.x] = 0;
    if (threadIdx.x == 0) { g_maxlvl = 0; g_bar_count = 0; }
}

// ---------------- K_roots ----------------
__global__ void k_roots(const float4* __restrict__ roots, float4* __restrict__ out) {
    int e = blockIdx.x * blockDim.x + threadIdx.x;
    int b = e >> 10;
    int rem = e & 1023;
    out[(size_t)b * ((NN * DD) >> 2) + rem] = roots[e];
}

// ---------------- K1: levels + histogram + max level ----------------
__global__ void k_levels(const int* __restrict__ idxs, const int* __restrict__ types) {
    __shared__ int   sIdx[NN * 2];
    __shared__ short sLvl[NN];
    __shared__ int   sHist[LMAX * TT];
    __shared__ int   sMax;
    int b = blockIdx.x, tid = threadIdx.x;

    for (int e = tid; e < NN * 2; e += 256) sIdx[e] = idxs[b * NN * 2 + e];
    for (int e = tid; e < NN; e += 256)     sLvl[e] = 0;
    for (int e = tid; e < LMAX * TT; e += 256) sHist[e] = 0;
    if (tid == 0) sMax = 0;
    __syncthreads();

    if (tid < 32) {
        volatile short* vl = sLvl;
        for (int base = RR; base < NN; base += 32) {
            int i = base + tid;
            int p0 = sIdx[2 * i], p1 = sIdx[2 * i + 1];
            while (true) {
                int l0 = vl[p0], l1 = vl[p1];
                int nl = 1 + (l0 > l1 ? l0 : l1);
                int ch = (nl != (int)vl[i]);
                __syncwarp();
                vl[i] = (short)nl;
                __syncwarp();
                if (!__ballot_sync(0xffffffffu, ch)) break;
            }
        }
    }
    __syncthreads();

    int mx = 0;
    for (int e = RR + tid; e < NN; e += 256) {
        int L = sLvl[e];
        if (L > mx) mx = L;
        g_lvl[b * NN + e] = (unsigned char)(L < 255 ? L : 255);
        if (L < LMAX) atomicAdd(&sHist[L * TT + types[b * NN + e]], 1);
    }
    atomicMax(&sMax, mx);
    __syncthreads();
    for (int e = tid; e < LMAX * TT; e += 256)
        if (sHist[e]) atomicAdd(&g_cnt[e], sHist[e]);
    if (tid == 0) atomicMax(&g_maxlvl, sMax);
}

// ---------------- K2: scan ----------------
__global__ void k_scan() {
    __shared__ int s[512];
    int tid = threadIdx.x;
    int v = g_cnt[tid];
    s[tid] = v;
    __syncthreads();
    for (int off = 1; off < 512; off <<= 1) {
        int x = (tid >= off) ? s[tid - off] : 0;
        __syncthreads();
        s[tid] += x;
        __syncthreads();
    }
    int excl = s[tid] - v;
    g_start[tid]  = excl;
    g_cursor[tid] = excl;
    if (tid == 511) g_start[512] = s[511];
}

// ---------------- K3: scatter ----------------
__global__ void k_scatter(const int* __restrict__ types) {
    int b = blockIdx.x, tid = threadIdx.x;
    for (int e = RR + tid; e < NN; e += 256) {
        int L = g_lvl[b * NN + e];
        if (L < LMAX) {
            int t = types[b * NN + e];
            int pos = atomicAdd(&g_cursor[L * TT + t], 1);
            g_list[pos] = ((unsigned)b << 11) | (unsigned)e;
        }
    }
}

// ---------------- grid barrier (single-wave persistent kernel) ----------------
__device__ __forceinline__ void grid_barrier(int nblocks) {
    __threadfence();
    __syncthreads();
    if (threadIdx.x == 0) {
        int gen = g_bar_gen;
        if (atomicAdd(&g_bar_count, 1) == nblocks - 1) {
            g_bar_count = 0;
            __threadfence();
            g_bar_gen = gen + 1;
        } else {
            while (g_bar_gen == gen) __nanosleep(32);
        }
    }
    __syncthreads();
}

// ---------------- K4: persistent per-level tiled GEMM, f32x2 math ----------------
__global__ void __launch_bounds__(128)
k_mlp(const float* __restrict__ W1, const float* __restrict__ bias1,
      const float* __restrict__ W2, const float* __restrict__ bias2,
      const int* __restrict__ idxs, float* __restrict__ out, int nblocks) {
    __shared__ float        sx[KD * XP];   // x tile transposed [k][row]; reused as h^T
    __shared__ unsigned int sV[TM];
    __shared__ int          sP0[TM], sP1[TM];
    __shared__ int          sMeta[9];
    __shared__ int          sTile[9];

    int tid = threadIdx.x;
    int tx = tid & 31, ty = tid >> 5;

    int Lmax = g_maxlvl;
    if (Lmax > LMAX - 1) Lmax = LMAX - 1;

    for (int L = 1; L <= Lmax; L++) {
        if (tid < 9) sMeta[tid] = g_start[L * TT + tid];
        __syncthreads();
        if (tid == 0) {
            int a = 0;
            for (int t = 0; t < TT; t++) {
                sTile[t] = a;
                a += (sMeta[t + 1] - sMeta[t] + TM - 1) >> 6;
            }
            sTile[8] = a;
        }
        __syncthreads();
        int tot = sTile[8];

        for (int tile = blockIdx.x; tile < tot; tile += nblocks) {
            int t = 0;
            while (tile >= sTile[t + 1]) t++;
            int base = sMeta[t] + ((tile - sTile[t]) << 6);
            int rows = sMeta[t + 1] - base; if (rows > TM) rows = TM;

            __syncthreads();   // protect sV/sx vs previous tile readers
            if (tid < TM) {
                unsigned int v = 0;
                if (tid < rows) v = g_list[base + tid];
                sV[tid]  = v;
                sP0[tid] = idxs[2 * v];
                sP1[tid] = idxs[2 * v + 1];
            }
            __syncthreads();

            // gather parent embeddings, transposed: sx[k][row]
            for (int e = tid; e < TM * 32; e += 128) {
                int row = e & 63, chunk = e >> 6;
                int which = chunk >> 4, seg = chunk & 15;
                unsigned int v = sV[row];
                int p = which ? sP1[row] : sP0[row];
                unsigned int node = (v & 0xFFFFF800u) | (unsigned)p;
                float4 vv = __ldcg((const float4*)out + (size_t)node * 16 + seg);
                int kk = (which << 6) + (seg << 2);
                sx[(kk    ) * XP + row] = vv.x;
                sx[(kk + 1) * XP + row] = vv.y;
                sx[(kk + 2) * XP + row] = vv.z;
                sx[(kk + 3) * XP + row] = vv.w;
            }
            __syncthreads();

            // GEMM1: h = x @ W1 + b1   (rows: ty*16..+15 as 8 row-pairs; cols: tx+32*cc)
            ull a1[8][4];
            {
                #pragma unroll
                for (int cc = 0; cc < 4; cc++) {
                    ull bsc = bcast2(bias1[t * HH + tx + (cc << 5)]);
                    #pragma unroll
                    for (int rp = 0; rp < 8; rp++) a1[rp][cc] = bsc;
                }
            }
            {
                const float* xrow = sx + (ty << 4);
                const float* w1b  = W1 + (size_t)t * KD * HH + tx;
                #pragma unroll 2
                for (int k = 0; k < KD; k++) {
                    const ulonglong2* xp = (const ulonglong2*)(xrow + k * XP);
                    ulonglong2 q0 = xp[0], q1 = xp[1], q2 = xp[2], q3 = xp[3];
                    ull xv[8] = {q0.x, q0.y, q1.x, q1.y, q2.x, q2.y, q3.x, q3.y};
                    const float* wr = w1b + (k << 7);
                    ull wb[4] = {bcast2(wr[0]), bcast2(wr[32]), bcast2(wr[64]), bcast2(wr[96])};
                    #pragma unroll
                    for (int rp = 0; rp < 8; rp++) {
                        #pragma unroll
                        for (int cc = 0; cc < 4; cc++)
                            a1[rp][cc] = fma2(xv[rp], wb[cc], a1[rp][cc]);
                    }
                }
            }
            __syncthreads();   // all x reads done before overwriting sx with h^T

            // GELU + transposed store: sx[hcol][row]
            #pragma unroll
            for (int rp = 0; rp < 8; rp++) {
                #pragma unroll
                for (int cc = 0; cc < 4; cc++) {
                    float u, v; unpack2(a1[rp][cc], u, v);
                    u = gelu_exact(u); v = gelu_exact(v);
                    *(ull*)&sx[(tx + (cc << 5)) * XP + (ty << 4) + (rp << 1)] = pack2(u, v);
                }
            }
            __syncthreads();

            // GEMM2: out = h @ W2 + b2   (cols: tx*2, tx*2+1)
            ull a2[8][2];
            {
                ull b0 = bcast2(bias2[t * DD + (tx << 1)]);
                ull b1v = bcast2(bias2[t * DD + (tx << 1) + 1]);
                #pragma unroll
                for (int rp = 0; rp < 8; rp++) { a2[rp][0] = b0; a2[rp][1] = b1v; }
            }
            {
                const float*  hrow = sx + (ty << 4);
                const float2* w2b  = (const float2*)(W2 + (size_t)t * KD * DD) + tx;
                #pragma unroll 2
                for (int k = 0; k < KD; k++) {
                    const ulonglong2* hp = (const ulonglong2*)(hrow + k * XP);
                    ulonglong2 q0 = hp[0], q1 = hp[1], q2 = hp[2], q3 = hp[3];
                    ull hv[8] = {q0.x, q0.y, q1.x, q1.y, q2.x, q2.y, q3.x, q3.y};
                    float2 w = w2b[k << 5];
                    ull wb0 = bcast2(w.x), wb1 = bcast2(w.y);
                    #pragma unroll
                    for (int rp = 0; rp < 8; rp++) {
                        a2[rp][0] = fma2(hv[rp], wb0, a2[rp][0]);
                        a2[rp][1] = fma2(hv[rp], wb1, a2[rp][1]);
                    }
                }
            }
            // store outputs
            {
                float2* outv2 = (float2*)out;
                #pragma unroll
                for (int rp = 0; rp < 8; rp++) {
                    int r0 = (ty << 4) + (rp << 1);
                    float u0, u1, v0, v1;
                    unpack2(a2[rp][0], u0, u1);
                    unpack2(a2[rp][1], v0, v1);
                    if (r0 < rows) {
                        float2 s; s.x = u0; s.y = v0;
                        outv2[(size_t)sV[r0] * 32 + tx] = s;
                    }
                    if (r0 + 1 < rows) {
                        float2 s; s.x = u1; s.y = v1;
                        outv2[(size_t)sV[r0 + 1] * 32 + tx] = s;
                    }
                }
            }
        }
        grid_barrier(nblocks);
    }
}

// ---------------- K5: sequential fallback for level >= LMAX ----------------
__global__ void k_cleanup(const float* __restrict__ W1, const float* __restrict__ bias1,
                          const float* __restrict__ W2, const float* __restrict__ bias2,
                          const int* __restrict__ idxs, const int* __restrict__ types,
                          float* __restrict__ out) {
    __shared__ int   sAny;
    __shared__ float sxc[KD];
    __shared__ float shc[HH];
    int b = blockIdx.x, tid = threadIdx.x;
    if (tid == 0) sAny = 0;
    __syncthreads();
    for (int e = RR + tid; e < NN; e += 128)
        if (g_lvl[b * NN + e] >= LMAX) sAny = 1;
    __syncthreads();
    if (!sAny) return;

    for (int i = RR; i < NN; i++) {
        if (g_lvl[b * NN + i] < LMAX) continue;
        int t = types[b * NN + i];
        int which = tid >> 6;
        int p = idxs[(b * NN + i) * 2 + which];
        sxc[tid] = out[((size_t)b * NN + p) * DD + (tid & 63)];
        __syncthreads();
        {
            float a = bias1[t * HH + tid];
            for (int kk = 0; kk < KD; kk++)
                a = fmaf(sxc[kk], W1[(size_t)(t * KD + kk) * HH + tid], a);
            shc[tid] = gelu_exact(a);
        }
        __syncthreads();
        if (tid < DD) {
            float a = bias2[t * DD + tid];
            for (int kk = 0; kk < HH; kk++)
                a = fmaf(shc[kk], W2[(size_t)(t * KD + kk) * DD + tid], a);
            out[((size_t)b * NN + i) * DD + tid] = a;
        }
        __syncthreads();
    }
}

// ---------------- launch ----------------
extern "C" void kernel_launch(void* const* d_in, const int* in_sizes, int n_in,
                              void* d_out, int out_size) {
    const float* roots = (const float*)d_in[0];
    const float* W1    = (const float*)d_in[1];
    const float* b1    = (const float*)d_in[2];
    const float* W2    = (const float*)d_in[3];
    const float* b2    = (const float*)d_in[4];
    const int*   idxs  = (const int*)d_in[5];
    const int*   types = (const int*)d_in[6];
    float* out = (float*)d_out;

    static int nblocks = 0;
    if (nblocks == 0) {
        int dev = 0, nsm = 0, bps = 0;
        cudaGetDevice(&dev);
        cudaDeviceGetAttribute(&nsm, cudaDevAttrMultiProcessorCount, dev);
        cudaOccupancyMaxActiveBlocksPerMultiprocessor(&bps, k_mlp, 128, 0);
        if (bps < 1) bps = 1;
        nblocks = nsm * bps;
    }

    k_zero<<<1, 512>>>();
    k_roots<<<(BB * RR * DD / 4) / 256, 256>>>((const float4*)roots, (float4*)out);
    k_levels<<<BB, 256>>>(idxs, types);
    k_scan<<<1, 512>>>();
    k_scatter<<<BB, 256>>>(types);
    k_mlp<<<nblocks, 128>>>(W1, b1, W2, b2, idxs, out, nblocks);
    k_cleanup<<<BB, 128>>>(W1, b1, W2, b2, idxs, types, out);
}